// round 15
// baseline (speedup 1.0000x reference)
#include <cuda_runtime.h>
#include <cooperative_groups.h>
#include <math.h>

namespace cg = cooperative_groups;

#define DD 384
#define HH 128
#define KK 128
#define NT 32
#define NXY 65536
#define MB 8
#define NKNOT 3
#define RC 4            // cluster size
#define NI1 32          // L1 output slice per CTA (4*32=128)
#define NI3 96          // L3 output slice per CTA (4*96=384)
#define PREF_CTAS 144   // prefetch CTAs in integrate launch

// coeff scratch: [c][k][t], t contiguous
__device__ float g_coeff[3 * KK * NT];

// coarse knots (fine-grid indices): 2 steps
__constant__ int c_kn[NKNOT] = {0, 16, 31};

#define NW1 (NI1 * DD)          // 12288 floats (48KB), float4-swizzled [j4][i^]
#define NW2 (HH * HH)           // 16384 (64KB)
#define NW3 (NI3 * HH)          // 12288 (48KB)
#define SMEM_FLOATS (NW1 + NW2 + NW3 + 8 * DD + HH + HH + 512 + HH + HH + DD + NT)
#define SMEM_BYTES  (SMEM_FLOATS * 4)

__device__ __forceinline__ void store_coeff(int i, int n, float val) {
    int k = i / 3, c = i - 3 * k;
    g_coeff[(c * KK + k) * NT + n] = val;
}

// bank swizzle for [j4][i] float4 layouts: i' = i ^ (j4 & 31)
__device__ __forceinline__ int swz(int j4, int i, int ni) {
    return j4 * ni + (i ^ (j4 & 31));
}

struct Ctx {
    const float4 *sW1, *sW2, *sW3;
    float *h1f, *h2, *part;
    float *h1p[RC];                 // peer h1f
    const float *b1, *b2, *b3;      // smem-resident bias copies
    int r;
};

// vout = W3 * elu(W2 * relu(W1*vin + b1) + b2) + b3
// i-sliced L1/L3, full local L2. Gathers via DSMEM remote stores + 2 cluster.syncs.
__device__ __forceinline__ void mlp(cg::cluster_group& cluster,
                                    const float* __restrict__ vin,
                                    float* const* voutp,
                                    const Ctx& cx, int tid)
{
    __syncthreads();                        // vin ready

    // ---- layer 1: 32 local outputs, full j=384. i=tid&31, p=tid>>5 (16) ----
    {
        const int i = tid & 31, p = tid >> 5;
        const float4* x4 = (const float4*)vin;
        float a0 = 0.f, a1 = 0.f, a2 = 0.f, a3 = 0.f;
        #pragma unroll
        for (int j4 = p * 6; j4 < p * 6 + 6; j4++) {
            float4 w = cx.sW1[swz(j4, i, NI1)];
            float4 x = x4[j4];
            a0 = fmaf(w.x, x.x, a0);
            a1 = fmaf(w.y, x.y, a1);
            a2 = fmaf(w.z, x.z, a2);
            a3 = fmaf(w.w, x.w, a3);
        }
        cx.part[p * NI1 + i] = (a0 + a1) + (a2 + a3);
    }
    __syncthreads();
    if (tid < NI1) {
        float s = cx.b1[cx.r * NI1 + tid];
        #pragma unroll
        for (int pp = 0; pp < 16; pp++) s += cx.part[pp * NI1 + tid];
        s = fmaxf(s, 0.f);
        #pragma unroll
        for (int rr = 0; rr < RC; rr++) cx.h1p[rr][cx.r * NI1 + tid] = s;
    }
    cluster.sync();

    // ---- layer 2: full 128 outputs local. i=tid&127, p=tid>>7 (4), ELU ----
    {
        const int i = tid & 127, p = tid >> 7;
        const float4* x4 = (const float4*)cx.h1f;
        float a0 = 0.f, a1 = 0.f, a2 = 0.f, a3 = 0.f;
        #pragma unroll
        for (int j4 = p * 8; j4 < p * 8 + 8; j4++) {
            float4 w = cx.sW2[swz(j4, i, HH)];
            float4 x = x4[j4];
            a0 = fmaf(w.x, x.x, a0);
            a1 = fmaf(w.y, x.y, a1);
            a2 = fmaf(w.z, x.z, a2);
            a3 = fmaf(w.w, x.w, a3);
        }
        cx.part[p * HH + i] = (a0 + a1) + (a2 + a3);
    }
    __syncthreads();
    if (tid < HH) {
        float s = cx.b2[tid] + cx.part[tid] + cx.part[HH + tid]
                + cx.part[2 * HH + tid] + cx.part[3 * HH + tid];
        cx.h2[tid] = s > 0.f ? s : expm1f(s);
    }
    __syncthreads();

    // ---- layer 3: 96 local outputs, j=128. tid<384: i=tid%96, p=tid/96 ----
    if (tid < 384) {
        const int i = tid % NI3, p = tid / NI3;
        const float4* x4 = (const float4*)cx.h2;
        float a0 = 0.f, a1 = 0.f, a2 = 0.f, a3 = 0.f;
        #pragma unroll
        for (int j4 = p * 8; j4 < p * 8 + 8; j4++) {
            float4 w = cx.sW3[swz(j4, i, NI3)];
            float4 x = x4[j4];
            a0 = fmaf(w.x, x.x, a0);
            a1 = fmaf(w.y, x.y, a1);
            a2 = fmaf(w.z, x.z, a2);
            a3 = fmaf(w.w, x.w, a3);
        }
        cx.part[p * NI3 + i] = (a0 + a1) + (a2 + a3);
    }
    __syncthreads();
    if (tid < NI3) {
        float s = cx.b3[cx.r * NI3 + tid] + cx.part[tid] + cx.part[NI3 + tid]
                + cx.part[2 * NI3 + tid] + cx.part[3 * NI3 + tid];
        #pragma unroll
        for (int rr = 0; rr < RC; rr++) voutp[rr][cx.r * NI3 + tid] = s;
    }
    cluster.sync();
}

// grid = 148 CTAs (37 clusters of 4). Cluster 0 integrates; CTAs 4..147
// prefetch the whole basis tensor into L2 and exit.
__global__ __launch_bounds__(512, 1) __cluster_dims__(RC, 1, 1)
void integrate_kernel(const float* __restrict__ tarr, const float* __restrict__ y0,
                      const float* __restrict__ W1, const float* __restrict__ b1,
                      const float* __restrict__ W2, const float* __restrict__ b2,
                      const float* __restrict__ W3, const float* __restrict__ b3,
                      const float* __restrict__ basis)
{
    extern __shared__ float smf[];
    const int tid = threadIdx.x;

    if (blockIdx.x >= RC) {
        // ---- L2 prefetch of basis (100 MB), 128B lines ----
        const char* bp = (const char*)basis;
        const size_t total = (size_t)KK * 3 * NXY * 4;
        const size_t stride = (size_t)PREF_CTAS * 512 * 128;
        size_t off = ((size_t)(blockIdx.x - RC) * 512 + tid) * 128;
        for (; off < total; off += stride)
            asm volatile("prefetch.global.L2 [%0];" :: "l"(bp + off));
        return;
    }

    cg::cluster_group cluster = cg::this_cluster();
    const int r = (int)cluster.block_rank();

    float4* sW1 = (float4*)smf;
    float4* sW2 = sW1 + NW1 / 4;
    float4* sW3 = sW2 + NW2 / 4;
    float* y    = smf + NW1 + NW2 + NW3;
    float* yold = y + DD;
    float* fold = yold + DD;
    float* v    = fold + DD;
    float* k1   = v + DD;
    float* k2   = k1 + DD;
    float* k3   = k2 + DD;
    float* k4   = k3 + DD;
    float* h1f  = k4 + DD;
    float* h2   = h1f + HH;
    float* part = h2 + HH;
    float* sb1  = part + 512;
    float* sb2  = sb1 + HH;
    float* sb3  = sb2 + HH;
    float* st   = sb3 + DD;

    Ctx cx;
    cx.sW1 = sW1; cx.sW2 = sW2; cx.sW3 = sW3;
    cx.h1f = h1f; cx.h2 = h2; cx.part = part;
    cx.b1 = sb1; cx.b2 = sb2; cx.b3 = sb3; cx.r = r;
    float* k1p[RC]; float* k2p[RC]; float* k3p[RC]; float* k4p[RC];
    #pragma unroll
    for (int rr = 0; rr < RC; rr++) {
        cx.h1p[rr] = (float*)cluster.map_shared_rank(h1f, rr);
        k1p[rr] = (float*)cluster.map_shared_rank(k1, rr);
        k2p[rr] = (float*)cluster.map_shared_rank(k2, rr);
        k3p[rr] = (float*)cluster.map_shared_rank(k3, rr);
        k4p[rr] = (float*)cluster.map_shared_rank(k4, rr);
    }

    // ---- preload: coalesced LDG.128, swizzled STS.128; biases+tarr to smem ----
    {
        const float4* W1f4 = (const float4*)W1;   // [128][96]
        for (int idx4 = tid; idx4 < NW1 / 4; idx4 += 512) {
            int i = idx4 / 96, j4 = idx4 - i * 96;
            sW1[swz(j4, i, NI1)] = W1f4[(r * NI1 + i) * 96 + j4];
        }
        const float4* W2f4 = (const float4*)W2;   // [128][32]
        for (int idx4 = tid; idx4 < NW2 / 4; idx4 += 512) {
            int i = idx4 >> 5, j4 = idx4 & 31;
            sW2[swz(j4, i, HH)] = W2f4[idx4];
        }
        const float4* W3f4 = (const float4*)W3;   // [384][32]
        for (int idx4 = tid; idx4 < NW3 / 4; idx4 += 512) {
            int i = idx4 >> 5, j4 = idx4 & 31;
            sW3[swz(j4, i, NI3)] = W3f4[(r * NI3 + i) * 32 + j4];
        }
        if (tid < HH) sb1[tid] = b1[tid];
        if (tid < HH) sb2[tid] = b2[tid];
        if (tid < DD) sb3[tid] = b3[tid];
        if (tid < NT) st[tid] = tarr[tid];
    }

    for (int i = tid; i < DD; i += 512) {
        float val = y0[i];
        y[i] = val;
        if (r == 0) store_coeff(i, 0, val);
    }

    for (int s = 0; s < NKNOT; s++) {
        mlp(cluster, y, k1p, cx, tid);

        if (s > 0 && r == 0) {
            const int n0 = c_kn[s - 1], n1 = c_kn[s];
            const float t0 = st[n0];
            const float hstep = st[n1] - t0;
            for (int n = n0 + 1; n < n1; n++) {
                const float th = (st[n] - t0) / hstep;
                const float th2 = th * th, th3 = th2 * th;
                const float cy0 = 1.f - 3.f * th2 + 2.f * th3;
                const float cy1 = 3.f * th2 - 2.f * th3;
                const float cf0 = hstep * (th - 2.f * th2 + th3);
                const float cf1 = hstep * (th3 - th2);
                for (int i = tid; i < DD; i += 512) {
                    float val = cy0 * yold[i] + cy1 * y[i]
                              + cf0 * fold[i] + cf1 * k1[i];
                    store_coeff(i, n, val);
                }
            }
            for (int i = tid; i < DD; i += 512)
                store_coeff(i, n1, y[i]);
        }
        if (s == NKNOT - 1) break;

        const float hstep = st[c_kn[s + 1]] - st[c_kn[s]];
        for (int i = tid; i < DD; i += 512) {
            yold[i] = y[i];
            fold[i] = k1[i];
            v[i] = y[i] + hstep * (1.f / 3.f) * k1[i];
        }

        mlp(cluster, v, k2p, cx, tid);
        for (int i = tid; i < DD; i += 512)
            v[i] = y[i] + hstep * (k2[i] - (1.f / 3.f) * k1[i]);

        mlp(cluster, v, k3p, cx, tid);
        for (int i = tid; i < DD; i += 512)
            v[i] = y[i] + hstep * (k1[i] - k2[i] + k3[i]);

        mlp(cluster, v, k4p, cx, tid);
        for (int i = tid; i < DD; i += 512)
            y[i] = y[i] + hstep * 0.125f * (k1[i] + 3.f * (k2[i] + k3[i]) + k4[i]);
    }
}

// ===== einsum: direct-LDG from warm L2, no staging, f32x2 FMAs =====
#define EPX 128          // px per CTA
#define ETH 128          // threads per CTA

__device__ __forceinline__ void fma2(unsigned long long& d,
                                     unsigned long long a, unsigned long long b) {
    asm("fma.rn.f32x2 %0, %1, %2, %0;" : "+l"(d) : "l"(a), "l"(b));
}
__device__ __forceinline__ unsigned long long dup2(float x) {
    unsigned long long d;
    asm("mov.b64 %0, {%1, %1};" : "=l"(d) : "r"(__float_as_uint(x)));
    return d;
}

__global__ __launch_bounds__(ETH, 7)
void einsum_kernel(const float* __restrict__ basis, float* __restrict__ out)
{
    __shared__ __align__(16) float ckt[KK * NT];      // 16 KB: coeff[c], [k][t]
    const int c = blockIdx.y;
    const int tid = threadIdx.x;
    const int pxg = tid & 31;          // 4-px group (32 groups = 128 px)
    const int tg = tid >> 5;           // t-group: 4 groups x 8 t
    const int xy0 = blockIdx.x * EPX;

    {   // ckt load: 1024 float4, 8 per thread
        const float4* src = (const float4*)(g_coeff + c * KK * NT);
        float4* dst = (float4*)ckt;
        #pragma unroll
        for (int h = 0; h < 8; h++) dst[tid + h * ETH] = src[tid + h * ETH];
    }
    __syncthreads();

    const float4* bb4 = (const float4*)(basis + (size_t)c * NXY + xy0);
    const int kst4 = 3 * NXY / 4;      // float4 stride between k-rows

    // acc[tp][px]: tp = t-pair (t=2*tp, 2*tp+1 within this tg's 8 t's), px 0..3
    unsigned long long acc[4][4];
    #pragma unroll
    for (int a = 0; a < 4; a++)
        #pragma unroll
        for (int b = 0; b < 4; b++) acc[a][b] = 0ull;

    const ulonglong2* ckp2 = (const ulonglong2*)ckt;  // c-pairs (t0t1),(t2t3)...

    #pragma unroll 4
    for (int k = 0; k < KK; k++) {
        const float4 bs = __ldg(bb4 + k * kst4 + pxg);
        const unsigned long long b0 = dup2(bs.x), b1 = dup2(bs.y);
        const unsigned long long b2 = dup2(bs.z), b3 = dup2(bs.w);
        const ulonglong2 cA = ckp2[k * 8 + tg * 2];      // (c_t0t1, c_t2t3)
        const ulonglong2 cB = ckp2[k * 8 + tg * 2 + 1];  // (c_t4t5, c_t6t7)
        fma2(acc[0][0], cA.x, b0); fma2(acc[0][1], cA.x, b1);
        fma2(acc[0][2], cA.x, b2); fma2(acc[0][3], cA.x, b3);
        fma2(acc[1][0], cA.y, b0); fma2(acc[1][1], cA.y, b1);
        fma2(acc[1][2], cA.y, b2); fma2(acc[1][3], cA.y, b3);
        fma2(acc[2][0], cB.x, b0); fma2(acc[2][1], cB.x, b1);
        fma2(acc[2][2], cB.x, b2); fma2(acc[2][3], cB.x, b3);
        fma2(acc[3][0], cB.y, b0); fma2(acc[3][1], cB.y, b1);
        fma2(acc[3][2], cB.y, b2); fma2(acc[3][3], cB.y, b3);
    }

    // stores: thread owns 4 consecutive px x 8 t; replicate over m. STG.128.
    const int px = xy0 + pxg * 4;
    #pragma unroll
    for (int tp = 0; tp < 4; tp++) {
        float2 p0 = *(float2*)&acc[tp][0];
        float2 p1 = *(float2*)&acc[tp][1];
        float2 p2 = *(float2*)&acc[tp][2];
        float2 p3 = *(float2*)&acc[tp][3];
        #pragma unroll
        for (int hi = 0; hi < 2; hi++) {
            const int t = tg * 8 + tp * 2 + hi;
            float4 v4 = hi ? make_float4(p0.y, p1.y, p2.y, p3.y)
                           : make_float4(p0.x, p1.x, p2.x, p3.x);
            float* base = out + ((size_t)(t * MB) * 3 + c) * NXY + px;
            #pragma unroll
            for (int m = 0; m < MB; m++)
                __stcs((float4*)(base + (size_t)m * (3 * NXY)), v4);
        }
    }
}

extern "C" void kernel_launch(void* const* d_in, const int* in_sizes, int n_in,
                              void* d_out, int out_size)
{
    // metadata order: grid0, t, init_coeffs, W1, b1, W2, b2, W3, b3, basis
    const float* tarr = (const float*)d_in[1];
    const float* y0   = (const float*)d_in[2];
    const float* W1   = (const float*)d_in[3];
    const float* b1   = (const float*)d_in[4];
    const float* W2   = (const float*)d_in[5];
    const float* b2   = (const float*)d_in[6];
    const float* W3   = (const float*)d_in[7];
    const float* b3   = (const float*)d_in[8];
    const float* basis = (const float*)d_in[9];
    float* out = (float*)d_out;

    cudaFuncSetAttribute(integrate_kernel,
                         cudaFuncAttributeMaxDynamicSharedMemorySize, SMEM_BYTES);
    integrate_kernel<<<RC + PREF_CTAS, 512, SMEM_BYTES>>>(
        tarr, y0, W1, b1, W2, b2, W3, b3, basis);
    einsum_kernel<<<dim3(NXY / EPX, 3), ETH>>>(basis, out);
}

// round 16
// speedup vs baseline: 1.1225x; 1.1225x over previous
#include <cuda_runtime.h>
#include <cooperative_groups.h>
#include <math.h>

namespace cg = cooperative_groups;

#define DD 384
#define HH 128
#define KK 128
#define NT 32
#define NXY 65536
#define MB 8
#define NKNOT 3
#define RC 4            // cluster size
#define NI1 32          // L1 output slice per CTA (4*32=128)
#define NI3 96          // L3 output slice per CTA (4*96=384)
#define PREF_CTAS 144   // prefetch CTAs in integrate launch

// coeff scratch: [c][k][t], t contiguous
__device__ float g_coeff[3 * KK * NT];

// coarse knots (fine-grid indices): 2 steps
__constant__ int c_kn[NKNOT] = {0, 16, 31};

#define NW1 (NI1 * DD)          // 12288 floats (48KB), float4-swizzled [j4][i^]
#define NW2 (HH * HH)           // 16384 (64KB)
#define NW3 (NI3 * HH)          // 12288 (48KB)
#define SMEM_FLOATS (NW1 + NW2 + NW3 + 8 * DD + HH + HH + 512 + HH + HH + DD + NT)
#define SMEM_BYTES  (SMEM_FLOATS * 4)

__device__ __forceinline__ void store_coeff(int i, int n, float val) {
    int k = i / 3, c = i - 3 * k;
    g_coeff[(c * KK + k) * NT + n] = val;
}

// bank swizzle for [j4][i] float4 layouts: i' = i ^ (j4 & 31)
__device__ __forceinline__ int swz(int j4, int i, int ni) {
    return j4 * ni + (i ^ (j4 & 31));
}

struct Ctx {
    const float4 *sW1, *sW2, *sW3;
    float *h1f, *h2, *part;
    float *h1p[RC];                 // peer h1f
    const float *b1, *b2, *b3;      // smem-resident bias copies
    int r;
};

// vout = W3 * elu(W2 * relu(W1*vin + b1) + b2) + b3
// i-sliced L1/L3, full local L2. Gathers via DSMEM remote stores + 2 cluster.syncs.
__device__ __forceinline__ void mlp(cg::cluster_group& cluster,
                                    const float* __restrict__ vin,
                                    float* const* voutp,
                                    const Ctx& cx, int tid)
{
    __syncthreads();                        // vin ready

    // ---- layer 1: 32 local outputs, full j=384. i=tid&31, p=tid>>5 (16) ----
    {
        const int i = tid & 31, p = tid >> 5;
        const float4* x4 = (const float4*)vin;
        float a0 = 0.f, a1 = 0.f, a2 = 0.f, a3 = 0.f;
        #pragma unroll
        for (int j4 = p * 6; j4 < p * 6 + 6; j4++) {
            float4 w = cx.sW1[swz(j4, i, NI1)];
            float4 x = x4[j4];
            a0 = fmaf(w.x, x.x, a0);
            a1 = fmaf(w.y, x.y, a1);
            a2 = fmaf(w.z, x.z, a2);
            a3 = fmaf(w.w, x.w, a3);
        }
        cx.part[p * NI1 + i] = (a0 + a1) + (a2 + a3);
    }
    __syncthreads();
    if (tid < NI1) {
        float s = cx.b1[cx.r * NI1 + tid];
        #pragma unroll
        for (int pp = 0; pp < 16; pp++) s += cx.part[pp * NI1 + tid];
        s = fmaxf(s, 0.f);
        #pragma unroll
        for (int rr = 0; rr < RC; rr++) cx.h1p[rr][cx.r * NI1 + tid] = s;
    }
    cluster.sync();

    // ---- layer 2: full 128 outputs local. i=tid&127, p=tid>>7 (4), ELU ----
    {
        const int i = tid & 127, p = tid >> 7;
        const float4* x4 = (const float4*)cx.h1f;
        float a0 = 0.f, a1 = 0.f, a2 = 0.f, a3 = 0.f;
        #pragma unroll
        for (int j4 = p * 8; j4 < p * 8 + 8; j4++) {
            float4 w = cx.sW2[swz(j4, i, HH)];
            float4 x = x4[j4];
            a0 = fmaf(w.x, x.x, a0);
            a1 = fmaf(w.y, x.y, a1);
            a2 = fmaf(w.z, x.z, a2);
            a3 = fmaf(w.w, x.w, a3);
        }
        cx.part[p * HH + i] = (a0 + a1) + (a2 + a3);
    }
    __syncthreads();
    if (tid < HH) {
        float s = cx.b2[tid] + cx.part[tid] + cx.part[HH + tid]
                + cx.part[2 * HH + tid] + cx.part[3 * HH + tid];
        cx.h2[tid] = s > 0.f ? s : expm1f(s);
    }
    __syncthreads();

    // ---- layer 3: 96 local outputs, j=128. tid<384: i=tid%96, p=tid/96 ----
    if (tid < 384) {
        const int i = tid % NI3, p = tid / NI3;
        const float4* x4 = (const float4*)cx.h2;
        float a0 = 0.f, a1 = 0.f, a2 = 0.f, a3 = 0.f;
        #pragma unroll
        for (int j4 = p * 8; j4 < p * 8 + 8; j4++) {
            float4 w = cx.sW3[swz(j4, i, NI3)];
            float4 x = x4[j4];
            a0 = fmaf(w.x, x.x, a0);
            a1 = fmaf(w.y, x.y, a1);
            a2 = fmaf(w.z, x.z, a2);
            a3 = fmaf(w.w, x.w, a3);
        }
        cx.part[p * NI3 + i] = (a0 + a1) + (a2 + a3);
    }
    __syncthreads();
    if (tid < NI3) {
        float s = cx.b3[cx.r * NI3 + tid] + cx.part[tid] + cx.part[NI3 + tid]
                + cx.part[2 * NI3 + tid] + cx.part[3 * NI3 + tid];
        #pragma unroll
        for (int rr = 0; rr < RC; rr++) voutp[rr][cx.r * NI3 + tid] = s;
    }
    cluster.sync();
}

// grid = 148 CTAs (37 clusters of 4). Cluster 0 integrates; CTAs 4..147
// prefetch the whole basis tensor into L2 and exit.
__global__ __launch_bounds__(512, 1) __cluster_dims__(RC, 1, 1)
void integrate_kernel(const float* __restrict__ tarr, const float* __restrict__ y0,
                      const float* __restrict__ W1, const float* __restrict__ b1,
                      const float* __restrict__ W2, const float* __restrict__ b2,
                      const float* __restrict__ W3, const float* __restrict__ b3,
                      const float* __restrict__ basis)
{
    extern __shared__ float smf[];
    const int tid = threadIdx.x;

    if (blockIdx.x >= RC) {
        // ---- L2 prefetch of basis (100 MB), 128B lines ----
        const char* bp = (const char*)basis;
        const size_t total = (size_t)KK * 3 * NXY * 4;
        const size_t stride = (size_t)PREF_CTAS * 512 * 128;
        size_t off = ((size_t)(blockIdx.x - RC) * 512 + tid) * 128;
        for (; off < total; off += stride)
            asm volatile("prefetch.global.L2 [%0];" :: "l"(bp + off));
        return;
    }

    cg::cluster_group cluster = cg::this_cluster();
    const int r = (int)cluster.block_rank();

    float4* sW1 = (float4*)smf;
    float4* sW2 = sW1 + NW1 / 4;
    float4* sW3 = sW2 + NW2 / 4;
    float* y    = smf + NW1 + NW2 + NW3;
    float* yold = y + DD;
    float* fold = yold + DD;
    float* v    = fold + DD;
    float* k1   = v + DD;
    float* k2   = k1 + DD;
    float* k3   = k2 + DD;
    float* k4   = k3 + DD;
    float* h1f  = k4 + DD;
    float* h2   = h1f + HH;
    float* part = h2 + HH;
    float* sb1  = part + 512;
    float* sb2  = sb1 + HH;
    float* sb3  = sb2 + HH;
    float* st   = sb3 + DD;

    Ctx cx;
    cx.sW1 = sW1; cx.sW2 = sW2; cx.sW3 = sW3;
    cx.h1f = h1f; cx.h2 = h2; cx.part = part;
    cx.b1 = sb1; cx.b2 = sb2; cx.b3 = sb3; cx.r = r;
    float* k1p[RC]; float* k2p[RC]; float* k3p[RC]; float* k4p[RC];
    #pragma unroll
    for (int rr = 0; rr < RC; rr++) {
        cx.h1p[rr] = (float*)cluster.map_shared_rank(h1f, rr);
        k1p[rr] = (float*)cluster.map_shared_rank(k1, rr);
        k2p[rr] = (float*)cluster.map_shared_rank(k2, rr);
        k3p[rr] = (float*)cluster.map_shared_rank(k3, rr);
        k4p[rr] = (float*)cluster.map_shared_rank(k4, rr);
    }

    // ---- preload: coalesced LDG.128, swizzled STS.128; biases+tarr to smem ----
    {
        const float4* W1f4 = (const float4*)W1;   // [128][96]
        for (int idx4 = tid; idx4 < NW1 / 4; idx4 += 512) {
            int i = idx4 / 96, j4 = idx4 - i * 96;
            sW1[swz(j4, i, NI1)] = W1f4[(r * NI1 + i) * 96 + j4];
        }
        const float4* W2f4 = (const float4*)W2;   // [128][32]
        for (int idx4 = tid; idx4 < NW2 / 4; idx4 += 512) {
            int i = idx4 >> 5, j4 = idx4 & 31;
            sW2[swz(j4, i, HH)] = W2f4[idx4];
        }
        const float4* W3f4 = (const float4*)W3;   // [384][32]
        for (int idx4 = tid; idx4 < NW3 / 4; idx4 += 512) {
            int i = idx4 >> 5, j4 = idx4 & 31;
            sW3[swz(j4, i, NI3)] = W3f4[(r * NI3 + i) * 32 + j4];
        }
        if (tid < HH) sb1[tid] = b1[tid];
        if (tid < HH) sb2[tid] = b2[tid];
        if (tid < DD) sb3[tid] = b3[tid];
        if (tid < NT) st[tid] = tarr[tid];
    }

    for (int i = tid; i < DD; i += 512) {
        float val = y0[i];
        y[i] = val;
        if (r == 0) store_coeff(i, 0, val);
    }

    for (int s = 0; s < NKNOT; s++) {
        mlp(cluster, y, k1p, cx, tid);

        if (s > 0 && r == 0) {
            const int n0 = c_kn[s - 1], n1 = c_kn[s];
            const float t0 = st[n0];
            const float hstep = st[n1] - t0;
            for (int n = n0 + 1; n < n1; n++) {
                const float th = (st[n] - t0) / hstep;
                const float th2 = th * th, th3 = th2 * th;
                const float cy0 = 1.f - 3.f * th2 + 2.f * th3;
                const float cy1 = 3.f * th2 - 2.f * th3;
                const float cf0 = hstep * (th - 2.f * th2 + th3);
                const float cf1 = hstep * (th3 - th2);
                for (int i = tid; i < DD; i += 512) {
                    float val = cy0 * yold[i] + cy1 * y[i]
                              + cf0 * fold[i] + cf1 * k1[i];
                    store_coeff(i, n, val);
                }
            }
            for (int i = tid; i < DD; i += 512)
                store_coeff(i, n1, y[i]);
        }
        if (s == NKNOT - 1) break;

        const float hstep = st[c_kn[s + 1]] - st[c_kn[s]];
        for (int i = tid; i < DD; i += 512) {
            yold[i] = y[i];
            fold[i] = k1[i];
            v[i] = y[i] + hstep * (1.f / 3.f) * k1[i];
        }

        mlp(cluster, v, k2p, cx, tid);
        for (int i = tid; i < DD; i += 512)
            v[i] = y[i] + hstep * (k2[i] - (1.f / 3.f) * k1[i]);

        mlp(cluster, v, k3p, cx, tid);
        for (int i = tid; i < DD; i += 512)
            v[i] = y[i] + hstep * (k1[i] - k2[i] + k3[i]);

        mlp(cluster, v, k4p, cx, tid);
        for (int i = tid; i < DD; i += 512)
            y[i] = y[i] + hstep * 0.125f * (k1[i] + 3.f * (k2[i] + k3[i]) + k4[i]);
    }
}

// ===== einsum: cp.async 2-stage, f32x2 FMAs, 8 CTAs/SM (24KB smem) =====
#define EPX 128          // px per CTA
#define ETH 128          // threads per CTA
#define CH 8             // k-rows per chunk
#define NCH (KK / CH)    // 16 chunks
#define ST 2             // pipeline stages
#define CHF (CH * EPX)   // 1024 floats per chunk buffer

__device__ __forceinline__ void cp16(float* s, const float* g) {
    unsigned sa = (unsigned)__cvta_generic_to_shared(s);
    asm volatile("cp.async.cg.shared.global [%0], [%1], 16;\n" :: "r"(sa), "l"(g));
}
__device__ __forceinline__ void cp_commit() {
    asm volatile("cp.async.commit_group;\n" ::: "memory");
}
template <int N>
__device__ __forceinline__ void cp_wait() {
    asm volatile("cp.async.wait_group %0;\n" :: "n"(N) : "memory");
}
__device__ __forceinline__ void fma2(unsigned long long& d,
                                     unsigned long long a, unsigned long long b) {
    asm("fma.rn.f32x2 %0, %1, %2, %0;" : "+l"(d) : "l"(a), "l"(b));
}
__device__ __forceinline__ unsigned long long dup2(float x) {
    unsigned long long d;
    asm("mov.b64 %0, {%1, %1};" : "=l"(d) : "r"(__float_as_uint(x)));
    return d;
}

__global__ __launch_bounds__(ETH, 8)
void einsum_kernel(const float* __restrict__ basis, float* __restrict__ out)
{
    __shared__ __align__(16) float ckt[KK * NT];      // 16 KB: coeff[c], [k][t]
    __shared__ __align__(16) float buf[ST][CHF];      // 2 x 4 KB basis stages
    const int c = blockIdx.y;
    const int tid = threadIdx.x;
    const int pxg = tid & 31;          // 4-px group (32 groups = 128 px)
    const int tg = tid >> 5;           // t-group: 4 groups x 8 t
    const int xy0 = blockIdx.x * EPX;
    const size_t kst = (size_t)3 * NXY;
    const float* bbase = basis + (size_t)c * NXY + xy0;

    {   // ckt load: 1024 float4, 8 per thread
        const float4* src = (const float4*)(g_coeff + c * KK * NT);
        float4* dst = (float4*)ckt;
        #pragma unroll
        for (int h = 0; h < 8; h++) dst[tid + h * ETH] = src[tid + h * ETH];
    }

    auto fill = [&](int ci, int b) {
        #pragma unroll
        for (int h = 0; h < 2; h++) {
            int idx = tid + h * ETH;          // 0..255
            int row = idx >> 5, f = idx & 31; // 8 rows x 32 float4
            cp16(&buf[b][row * EPX + f * 4],
                 bbase + (size_t)(ci * CH + row) * kst + f * 4);
        }
    };

    fill(0, 0); cp_commit();

    // acc[tp][px]: tp = t-pair (t=2*tp, 2*tp+1 within this tg's 8 t's), px 0..3
    unsigned long long acc[4][4];
    #pragma unroll
    for (int a = 0; a < 4; a++)
        #pragma unroll
        for (int b = 0; b < 4; b++) acc[a][b] = 0ull;

    const ulonglong2* ckp2 = (const ulonglong2*)ckt;  // c-pairs (t0t1),(t2t3)...

    for (int ci = 0; ci < NCH; ci++) {
        cp_wait<0>();
        __syncthreads();                    // chunk ci ready; prev buf reads done
        // prefetch next chunk into the other buffer before computing
        const int nc = ci + 1;
        if (nc < NCH) fill(nc, nc & 1);
        cp_commit();

        const float4* bs4 = (const float4*)buf[ci & 1];
        #pragma unroll
        for (int kr = 0; kr < CH; kr++) {
            const int k = ci * CH + kr;
            const float4 bs = bs4[kr * (EPX / 4) + pxg];
            const unsigned long long b0 = dup2(bs.x), b1 = dup2(bs.y);
            const unsigned long long b2 = dup2(bs.z), b3 = dup2(bs.w);
            const ulonglong2 cA = ckp2[k * 8 + tg * 2];
            const ulonglong2 cB = ckp2[k * 8 + tg * 2 + 1];
            fma2(acc[0][0], cA.x, b0); fma2(acc[0][1], cA.x, b1);
            fma2(acc[0][2], cA.x, b2); fma2(acc[0][3], cA.x, b3);
            fma2(acc[1][0], cA.y, b0); fma2(acc[1][1], cA.y, b1);
            fma2(acc[1][2], cA.y, b2); fma2(acc[1][3], cA.y, b3);
            fma2(acc[2][0], cB.x, b0); fma2(acc[2][1], cB.x, b1);
            fma2(acc[2][2], cB.x, b2); fma2(acc[2][3], cB.x, b3);
            fma2(acc[3][0], cB.y, b0); fma2(acc[3][1], cB.y, b1);
            fma2(acc[3][2], cB.y, b2); fma2(acc[3][3], cB.y, b3);
        }
        __syncthreads();                    // done reading buf before next fill overwrites
    }

    // stores: thread owns 4 consecutive px x 8 t; replicate over m. STG.128.
    const int px = xy0 + pxg * 4;
    #pragma unroll
    for (int tp = 0; tp < 4; tp++) {
        float2 p0 = *(float2*)&acc[tp][0];
        float2 p1 = *(float2*)&acc[tp][1];
        float2 p2 = *(float2*)&acc[tp][2];
        float2 p3 = *(float2*)&acc[tp][3];
        #pragma unroll
        for (int hi = 0; hi < 2; hi++) {
            const int t = tg * 8 + tp * 2 + hi;
            float4 v4 = hi ? make_float4(p0.y, p1.y, p2.y, p3.y)
                           : make_float4(p0.x, p1.x, p2.x, p3.x);
            float* base = out + ((size_t)(t * MB) * 3 + c) * NXY + px;
            #pragma unroll
            for (int m = 0; m < MB; m++)
                __stcs((float4*)(base + (size_t)m * (3 * NXY)), v4);
        }
    }
}

extern "C" void kernel_launch(void* const* d_in, const int* in_sizes, int n_in,
                              void* d_out, int out_size)
{
    // metadata order: grid0, t, init_coeffs, W1, b1, W2, b2, W3, b3, basis
    const float* tarr = (const float*)d_in[1];
    const float* y0   = (const float*)d_in[2];
    const float* W1   = (const float*)d_in[3];
    const float* b1   = (const float*)d_in[4];
    const float* W2   = (const float*)d_in[5];
    const float* b2   = (const float*)d_in[6];
    const float* W3   = (const float*)d_in[7];
    const float* b3   = (const float*)d_in[8];
    const float* basis = (const float*)d_in[9];
    float* out = (float*)d_out;

    cudaFuncSetAttribute(integrate_kernel,
                         cudaFuncAttributeMaxDynamicSharedMemorySize, SMEM_BYTES);
    integrate_kernel<<<RC + PREF_CTAS, 512, SMEM_BYTES>>>(
        tarr, y0, W1, b1, W2, b2, W3, b3, basis);
    einsum_kernel<<<dim3(NXY / EPX, 3), ETH>>>(basis, out);
}

// round 17
// speedup vs baseline: 1.2588x; 1.1214x over previous
#include <cuda_runtime.h>
#include <cooperative_groups.h>
#include <math.h>

namespace cg = cooperative_groups;

#define DD 384
#define HH 128
#define KK 128
#define NT 32
#define NXY 65536
#define MB 8
#define NKNOT 3
#define RC 4            // cluster size
#define NI1 32          // L1 output slice per CTA (4*32=128)
#define NI3 96          // L3 output slice per CTA (4*96=384)
#define PREF_CTAS 144   // prefetch CTAs in integrate launch

// coeff scratch: [c][k][t], t contiguous
__device__ float g_coeff[3 * KK * NT];

// coarse knots (fine-grid indices): 2 steps
__constant__ int c_kn[NKNOT] = {0, 16, 31};

// integrator smem: state vectors + reduce buffers + biases + tarr (no weights!)
#define SMEM_FLOATS (8 * DD + HH + HH + 512 + HH + HH + DD + NT)
#define SMEM_BYTES  (SMEM_FLOATS * 4)

__device__ __forceinline__ void store_coeff(int i, int n, float val) {
    int k = i / 3, c = i - 3 * k;
    g_coeff[(c * KK + k) * NT + n] = val;
}

struct Ctx {
    float *h1f, *h2, *part;
    const float *b1, *b2, *b3;      // smem-resident bias copies
    int r;
};

// vout = W3 * elu(W2 * relu(W1*vin + b1) + b2) + b3
// Weights live in REGISTERS (w1r/w2r/w3r, per-thread slices, loaded once).
// i-sliced L1/L3, full local L2. Gathers via DSMEM remote stores + 2 cluster.syncs.
__device__ __forceinline__ void mlp(cg::cluster_group& cluster,
                                    const float* __restrict__ vin,
                                    float* __restrict__ vout_local,
                                    const float4 w1r[6], const float4 w2r[8],
                                    const float4 w3r[8],
                                    const Ctx& cx, int tid)
{
    __syncthreads();                        // vin ready

    // ---- layer 1: 32 local outputs, full j=384. i=tid&31, p=tid>>5 (16) ----
    {
        const int i = tid & 31, p = tid >> 5;
        const float4* x4 = (const float4*)vin;
        float a0 = 0.f, a1 = 0.f, a2 = 0.f, a3 = 0.f;
        #pragma unroll
        for (int q = 0; q < 6; q++) {
            float4 x = x4[p * 6 + q];
            a0 = fmaf(w1r[q].x, x.x, a0);
            a1 = fmaf(w1r[q].y, x.y, a1);
            a2 = fmaf(w1r[q].z, x.z, a2);
            a3 = fmaf(w1r[q].w, x.w, a3);
        }
        cx.part[p * NI1 + i] = (a0 + a1) + (a2 + a3);
    }
    __syncthreads();
    if (tid < NI1) {
        float s = cx.b1[cx.r * NI1 + tid];
        #pragma unroll
        for (int pp = 0; pp < 16; pp++) s += cx.part[pp * NI1 + tid];
        s = fmaxf(s, 0.f);
        #pragma unroll
        for (int rr = 0; rr < RC; rr++) {
            float* ph = (float*)cluster.map_shared_rank(cx.h1f, rr);
            ph[cx.r * NI1 + tid] = s;
        }
    }
    cluster.sync();

    // ---- layer 2: full 128 outputs local. i=tid&127, p=tid>>7 (4), ELU ----
    {
        const int i = tid & 127, p = tid >> 7;
        const float4* x4 = (const float4*)cx.h1f;
        float a0 = 0.f, a1 = 0.f, a2 = 0.f, a3 = 0.f;
        #pragma unroll
        for (int q = 0; q < 8; q++) {
            float4 x = x4[p * 8 + q];
            a0 = fmaf(w2r[q].x, x.x, a0);
            a1 = fmaf(w2r[q].y, x.y, a1);
            a2 = fmaf(w2r[q].z, x.z, a2);
            a3 = fmaf(w2r[q].w, x.w, a3);
        }
        cx.part[p * HH + i] = (a0 + a1) + (a2 + a3);
    }
    __syncthreads();
    if (tid < HH) {
        float s = cx.b2[tid] + cx.part[tid] + cx.part[HH + tid]
                + cx.part[2 * HH + tid] + cx.part[3 * HH + tid];
        cx.h2[tid] = s > 0.f ? s : expm1f(s);
    }
    __syncthreads();

    // ---- layer 3: 96 local outputs, j=128. tid<384: i=tid%96, p=tid/96 ----
    if (tid < 384) {
        const int i = tid % NI3, p = tid / NI3;
        const float4* x4 = (const float4*)cx.h2;
        float a0 = 0.f, a1 = 0.f, a2 = 0.f, a3 = 0.f;
        #pragma unroll
        for (int q = 0; q < 8; q++) {
            float4 x = x4[p * 8 + q];
            a0 = fmaf(w3r[q].x, x.x, a0);
            a1 = fmaf(w3r[q].y, x.y, a1);
            a2 = fmaf(w3r[q].z, x.z, a2);
            a3 = fmaf(w3r[q].w, x.w, a3);
        }
        cx.part[p * NI3 + i] = (a0 + a1) + (a2 + a3);
    }
    __syncthreads();
    if (tid < NI3) {
        float s = cx.b3[cx.r * NI3 + tid] + cx.part[tid] + cx.part[NI3 + tid]
                + cx.part[2 * NI3 + tid] + cx.part[3 * NI3 + tid];
        #pragma unroll
        for (int rr = 0; rr < RC; rr++) {
            float* pv = (float*)cluster.map_shared_rank(vout_local, rr);
            pv[cx.r * NI3 + tid] = s;
        }
    }
    cluster.sync();
}

// grid = 148 CTAs (37 clusters of 4). Cluster 0 integrates; CTAs 4..147
// prefetch the whole basis tensor into L2 and exit.
__global__ __launch_bounds__(512, 1) __cluster_dims__(RC, 1, 1)
void integrate_kernel(const float* __restrict__ tarr, const float* __restrict__ y0,
                      const float* __restrict__ W1, const float* __restrict__ b1,
                      const float* __restrict__ W2, const float* __restrict__ b2,
                      const float* __restrict__ W3, const float* __restrict__ b3,
                      const float* __restrict__ basis)
{
    extern __shared__ float smf[];
    const int tid = threadIdx.x;

    if (blockIdx.x >= RC) {
        // ---- L2 prefetch of basis (100 MB), 128B lines ----
        const char* bp = (const char*)basis;
        const size_t total = (size_t)KK * 3 * NXY * 4;
        const size_t stride = (size_t)PREF_CTAS * 512 * 128;
        size_t off = ((size_t)(blockIdx.x - RC) * 512 + tid) * 128;
        for (; off < total; off += stride)
            asm volatile("prefetch.global.L2 [%0];" :: "l"(bp + off));
        return;
    }

    cg::cluster_group cluster = cg::this_cluster();
    const int r = (int)cluster.block_rank();

    float* y    = smf;
    float* yold = y + DD;
    float* fold = yold + DD;
    float* v    = fold + DD;
    float* k1   = v + DD;
    float* k2   = k1 + DD;
    float* k3   = k2 + DD;
    float* k4   = k3 + DD;
    float* h1f  = k4 + DD;
    float* h2   = h1f + HH;
    float* part = h2 + HH;
    float* sb1  = part + 512;
    float* sb2  = sb1 + HH;
    float* sb3  = sb2 + HH;
    float* st   = sb3 + DD;

    Ctx cx;
    cx.h1f = h1f; cx.h2 = h2; cx.part = part;
    cx.b1 = sb1; cx.b2 = sb2; cx.b3 = sb3; cx.r = r;

    // ---- load per-thread weight slices into registers ----
    float4 w1r[6], w2r[8], w3r[8];
    {
        const float4* W1f4 = (const float4*)W1;   // [128][96]
        const int i1 = tid & 31, p1 = tid >> 5;
        #pragma unroll
        for (int q = 0; q < 6; q++)
            w1r[q] = W1f4[(r * NI1 + i1) * 96 + p1 * 6 + q];

        const float4* W2f4 = (const float4*)W2;   // [128][32]
        const int i2 = tid & 127, p2 = tid >> 7;
        #pragma unroll
        for (int q = 0; q < 8; q++)
            w2r[q] = W2f4[i2 * 32 + p2 * 8 + q];

        const float4* W3f4 = (const float4*)W3;   // [384][32]
        if (tid < 384) {
            const int i3 = tid % NI3, p3 = tid / NI3;
            #pragma unroll
            for (int q = 0; q < 8; q++)
                w3r[q] = W3f4[(r * NI3 + i3) * 32 + p3 * 8 + q];
        }
        if (tid < HH) sb1[tid] = b1[tid];
        if (tid < HH) sb2[tid] = b2[tid];
        if (tid < DD) sb3[tid] = b3[tid];
        if (tid < NT) st[tid] = tarr[tid];
    }

    for (int i = tid; i < DD; i += 512) {
        float val = y0[i];
        y[i] = val;
        if (r == 0) store_coeff(i, 0, val);
    }

    for (int s = 0; s < NKNOT; s++) {
        mlp(cluster, y, k1, w1r, w2r, w3r, cx, tid);

        if (s > 0 && r == 0) {
            const int n0 = c_kn[s - 1], n1 = c_kn[s];
            const float t0 = st[n0];
            const float hstep = st[n1] - t0;
            for (int n = n0 + 1; n < n1; n++) {
                const float th = (st[n] - t0) / hstep;
                const float th2 = th * th, th3 = th2 * th;
                const float cy0 = 1.f - 3.f * th2 + 2.f * th3;
                const float cy1 = 3.f * th2 - 2.f * th3;
                const float cf0 = hstep * (th - 2.f * th2 + th3);
                const float cf1 = hstep * (th3 - th2);
                for (int i = tid; i < DD; i += 512) {
                    float val = cy0 * yold[i] + cy1 * y[i]
                              + cf0 * fold[i] + cf1 * k1[i];
                    store_coeff(i, n, val);
                }
            }
            for (int i = tid; i < DD; i += 512)
                store_coeff(i, n1, y[i]);
        }
        if (s == NKNOT - 1) break;

        const float hstep = st[c_kn[s + 1]] - st[c_kn[s]];
        for (int i = tid; i < DD; i += 512) {
            yold[i] = y[i];
            fold[i] = k1[i];
            v[i] = y[i] + hstep * (1.f / 3.f) * k1[i];
        }

        mlp(cluster, v, k2, w1r, w2r, w3r, cx, tid);
        for (int i = tid; i < DD; i += 512)
            v[i] = y[i] + hstep * (k2[i] - (1.f / 3.f) * k1[i]);

        mlp(cluster, v, k3, w1r, w2r, w3r, cx, tid);
        for (int i = tid; i < DD; i += 512)
            v[i] = y[i] + hstep * (k1[i] - k2[i] + k3[i]);

        mlp(cluster, v, k4, w1r, w2r, w3r, cx, tid);
        for (int i = tid; i < DD; i += 512)
            y[i] = y[i] + hstep * 0.125f * (k1[i] + 3.f * (k2[i] + k3[i]) + k4[i]);
    }
}

// ===== einsum: cp.async 3-stage (R14 measured-best config), f32x2 FMAs =====
#define EPX 128          // px per CTA
#define ETH 128          // threads per CTA
#define CH 8             // k-rows per chunk
#define NCH (KK / CH)    // 16 chunks
#define ST 3             // pipeline stages
#define CHF (CH * EPX)   // 1024 floats per chunk buffer

__device__ __forceinline__ void cp16(float* s, const float* g) {
    unsigned sa = (unsigned)__cvta_generic_to_shared(s);
    asm volatile("cp.async.cg.shared.global [%0], [%1], 16;\n" :: "r"(sa), "l"(g));
}
__device__ __forceinline__ void cp_commit() {
    asm volatile("cp.async.commit_group;\n" ::: "memory");
}
template <int N>
__device__ __forceinline__ void cp_wait() {
    asm volatile("cp.async.wait_group %0;\n" :: "n"(N) : "memory");
}
__device__ __forceinline__ void fma2(unsigned long long& d,
                                     unsigned long long a, unsigned long long b) {
    asm("fma.rn.f32x2 %0, %1, %2, %0;" : "+l"(d) : "l"(a), "l"(b));
}
__device__ __forceinline__ unsigned long long dup2(float x) {
    unsigned long long d;
    asm("mov.b64 %0, {%1, %1};" : "=l"(d) : "r"(__float_as_uint(x)));
    return d;
}

__global__ __launch_bounds__(ETH, 8)
void einsum_kernel(const float* __restrict__ basis, float* __restrict__ out)
{
    __shared__ __align__(16) float ckt[KK * NT];      // 16 KB: coeff[c], [k][t]
    __shared__ __align__(16) float buf[ST][CHF];      // 3 x 4 KB basis stages
    const int c = blockIdx.y;
    const int tid = threadIdx.x;
    const int pxg = tid & 31;          // 4-px group (32 groups = 128 px)
    const int tg = tid >> 5;           // t-group: 4 groups x 8 t
    const int xy0 = blockIdx.x * EPX;
    const size_t kst = (size_t)3 * NXY;
    const float* bbase = basis + (size_t)c * NXY + xy0;

    {   // ckt load: 1024 float4, 8 per thread
        const float4* src = (const float4*)(g_coeff + c * KK * NT);
        float4* dst = (float4*)ckt;
        #pragma unroll
        for (int h = 0; h < 8; h++) dst[tid + h * ETH] = src[tid + h * ETH];
    }

    auto fill = [&](int ci, int b) {
        #pragma unroll
        for (int h = 0; h < 2; h++) {
            int idx = tid + h * ETH;          // 0..255
            int row = idx >> 5, f = idx & 31; // 8 rows x 32 float4
            cp16(&buf[b][row * EPX + f * 4],
                 bbase + (size_t)(ci * CH + row) * kst + f * 4);
        }
    };

    #pragma unroll
    for (int pc = 0; pc < ST - 1; pc++) { fill(pc, pc); cp_commit(); }

    // acc[tp][px]: tp = t-pair (t=2*tp, 2*tp+1 within this tg's 8 t's), px 0..3
    unsigned long long acc[4][4];
    #pragma unroll
    for (int a = 0; a < 4; a++)
        #pragma unroll
        for (int b = 0; b < 4; b++) acc[a][b] = 0ull;

    const ulonglong2* ckp2 = (const ulonglong2*)ckt;  // c-pairs (t0t1),(t2t3)...

    for (int ci = 0; ci < NCH; ci++) {
        cp_wait<ST - 2>();
        __syncthreads();                    // chunk ci ready; prev buf reads done
        const int b = ci % ST;
        const float4* bs4 = (const float4*)buf[b];
        #pragma unroll
        for (int kr = 0; kr < CH; kr++) {
            const int k = ci * CH + kr;
            const float4 bs = bs4[kr * (EPX / 4) + pxg];
            const unsigned long long b0 = dup2(bs.x), b1 = dup2(bs.y);
            const unsigned long long b2 = dup2(bs.z), b3 = dup2(bs.w);
            const ulonglong2 cA = ckp2[k * 8 + tg * 2];
            const ulonglong2 cB = ckp2[k * 8 + tg * 2 + 1];
            fma2(acc[0][0], cA.x, b0); fma2(acc[0][1], cA.x, b1);
            fma2(acc[0][2], cA.x, b2); fma2(acc[0][3], cA.x, b3);
            fma2(acc[1][0], cA.y, b0); fma2(acc[1][1], cA.y, b1);
            fma2(acc[1][2], cA.y, b2); fma2(acc[1][3], cA.y, b3);
            fma2(acc[2][0], cB.x, b0); fma2(acc[2][1], cB.x, b1);
            fma2(acc[2][2], cB.x, b2); fma2(acc[2][3], cB.x, b3);
            fma2(acc[3][0], cB.y, b0); fma2(acc[3][1], cB.y, b1);
            fma2(acc[3][2], cB.y, b2); fma2(acc[3][3], cB.y, b3);
        }
        __syncthreads();                    // done reading buf b
        const int nc = ci + ST - 1;
        if (nc < NCH) fill(nc, nc % ST);
        cp_commit();
    }

    // stores: thread owns 4 consecutive px x 8 t; replicate over m. STG.128.
    const int px = xy0 + pxg * 4;
    #pragma unroll
    for (int tp = 0; tp < 4; tp++) {
        float2 p0 = *(float2*)&acc[tp][0];
        float2 p1 = *(float2*)&acc[tp][1];
        float2 p2 = *(float2*)&acc[tp][2];
        float2 p3 = *(float2*)&acc[tp][3];
        #pragma unroll
        for (int hi = 0; hi < 2; hi++) {
            const int t = tg * 8 + tp * 2 + hi;
            float4 v4 = hi ? make_float4(p0.y, p1.y, p2.y, p3.y)
                           : make_float4(p0.x, p1.x, p2.x, p3.x);
            float* base = out + ((size_t)(t * MB) * 3 + c) * NXY + px;
            #pragma unroll
            for (int m = 0; m < MB; m++)
                __stcs((float4*)(base + (size_t)m * (3 * NXY)), v4);
        }
    }
}

extern "C" void kernel_launch(void* const* d_in, const int* in_sizes, int n_in,
                              void* d_out, int out_size)
{
    // metadata order: grid0, t, init_coeffs, W1, b1, W2, b2, W3, b3, basis
    const float* tarr = (const float*)d_in[1];
    const float* y0   = (const float*)d_in[2];
    const float* W1   = (const float*)d_in[3];
    const float* b1   = (const float*)d_in[4];
    const float* W2   = (const float*)d_in[5];
    const float* b2   = (const float*)d_in[6];
    const float* W3   = (const float*)d_in[7];
    const float* b3   = (const float*)d_in[8];
    const float* basis = (const float*)d_in[9];
    float* out = (float*)d_out;

    cudaFuncSetAttribute(integrate_kernel,
                         cudaFuncAttributeMaxDynamicSharedMemorySize, SMEM_BYTES);
    integrate_kernel<<<RC + PREF_CTAS, 512, SMEM_BYTES>>>(
        tarr, y0, W1, b1, W2, b2, W3, b3, basis);
    einsum_kernel<<<dim3(NXY / EPX, 3), ETH>>>(basis, out);
}